// round 10
// baseline (speedup 1.0000x reference)
#include <cuda_runtime.h>

// Problem shape (fixed by dataset): D=1024, P=256, R=64, K=1024
#define D_DIRS 1024
#define P_PTS  256
#define R_RANK 64
#define K_SUB  1024

#define NCHUNK  32
#define CHUNK_D (D_DIRS / NCHUNK)     // 32 d's per chunk

#define NB_DATA     (2 * D_DIRS)      // 2048 streaming blocks
#define NB_PREFETCH 16
#define NB_PARTIAL  (NCHUNK * 4)      // 128
#define NB_COMBINE  64
#define B_PREFETCH  NB_DATA
#define B_PARTIAL   (NB_DATA + NB_PREFETCH)           // 2064
#define B_COMBINE   (B_PARTIAL + NB_PARTIAL)          // 2192
#define NB_TOTAL    (B_COMBINE + NB_COMBINE)          // 2256

// Scratch (allocation-free rule: __device__ globals)
__device__ float g_asum[D_DIRS * R_RANK];
__device__ float g_bsum[D_DIRS * R_RANK];
__device__ float g_part[NCHUNK * R_RANK * R_RANK];   // 512 KB, fully rewritten
__device__ float g_sink[NB_PREFETCH];
__device__ unsigned g_ready[NCHUNK];                 // per-chunk arrivals (target 64)
__device__ unsigned g_parts;                         // partial blocks done (target 128)
__device__ unsigned g_done;                          // combine blocks done (for reset)

__device__ __forceinline__ unsigned ld_acq(const unsigned* p)
{
    unsigned v;
    asm volatile("ld.acquire.gpu.global.u32 %0, [%1];" : "=r"(v) : "l"(p));
    return v;
}

__device__ __forceinline__ void spin_until(const unsigned* ctr, unsigned target)
{
    if (threadIdx.x == 0) {
        while (ld_acq(ctr) < target) __nanosleep(64);
    }
    __syncthreads();
}

// ---------------------------------------------------------------------------
// Single mega-kernel, role by blockIdx.x (spinners have the HIGHEST indices
// so they are dispatched last; all dependencies point at lower indices).
// ---------------------------------------------------------------------------
__global__ __launch_bounds__(256) void lowrank_kernel(
    const float* __restrict__ atten, const float* __restrict__ rad,
    const float* __restrict__ F, float* __restrict__ out)
{
    __shared__ __align__(16) float pool[5120];   // 20 KB, role-dependent
    const int b = blockIdx.x;
    const int t = threadIdx.x;

    // ======================= streaming reduce blocks =======================
    if (b < NB_DATA) {
        const bool is_b = (b >= D_DIRS);
        const int d = b & (D_DIRS - 1);
        const float* __restrict__ src = is_b ? rad : atten;
        float* __restrict__ dst = is_b ? g_bsum : g_asum;

        const float4* __restrict__ in =
            reinterpret_cast<const float4*>(src) + (size_t)d * (P_PTS * R_RANK / 4);

        float4 acc = make_float4(0.f, 0.f, 0.f, 0.f);
        #pragma unroll
        for (int i = 0; i < 16; i++) {
            float4 v = __ldcs(&in[i * 256 + t]);
            acc.x += v.x; acc.y += v.y; acc.z += v.z; acc.w += v.w;
        }

        float4* s = reinterpret_cast<float4*>(pool);
        s[t] = acc;
        __syncthreads();

        if (t < 16) {
            float4 sum = s[t];
            #pragma unroll
            for (int j = 1; j < 16; j++) {
                float4 v = s[j * 16 + t];
                sum.x += v.x; sum.y += v.y; sum.z += v.z; sum.w += v.w;
            }
            reinterpret_cast<float4*>(dst + d * R_RANK)[t] = sum;
            __threadfence();
        }
        __syncthreads();
        if (t == 0)
            atomicAdd(&g_ready[d >> 5], 1u);   // chunk = d / CHUNK_D
        return;
    }

    // ======================= F prefetch blocks =============================
    if (b < B_PARTIAL) {
        const int pb = b - B_PREFETCH;
        const float4* __restrict__ f4 =
            reinterpret_cast<const float4*>(F) + (size_t)pb * 1024;
        float4 acc = make_float4(0.f, 0.f, 0.f, 0.f);
        #pragma unroll
        for (int i = 0; i < 4; i++) {
            float4 v = f4[i * 256 + t];
            acc.x += v.x; acc.y += v.y; acc.z += v.z; acc.w += v.w;
        }
        if (t == 0) g_sink[pb] = acc.x + acc.y + acc.z + acc.w;
        return;
    }

    // ======================= partial-M blocks ==============================
    if (b < B_COMBINE) {
        const int pb = b - B_PARTIAL;
        const int c  = pb >> 2;    // chunk
        const int q  = pb & 3;     // r1 quarter

        spin_until(&g_ready[c], 2 * CHUNK_D);   // 64 arrivals (a + b per d)

        float* sA = pool;                 // [32][64] = 8 KB
        float* sB = pool + CHUNK_D * R_RANK;

        const float4* __restrict__ a4 =
            reinterpret_cast<const float4*>(g_asum) + (size_t)c * (CHUNK_D * R_RANK / 4);
        const float4* __restrict__ b4 =
            reinterpret_cast<const float4*>(g_bsum) + (size_t)c * (CHUNK_D * R_RANK / 4);
        #pragma unroll
        for (int i = 0; i < 2; i++) {
            reinterpret_cast<float4*>(sA)[i * 256 + t] = a4[i * 256 + t];
            reinterpret_cast<float4*>(sB)[i * 256 + t] = b4[i * 256 + t];
        }
        __syncthreads();

        const int r1  = q * 16 + (t >> 4);
        const int r2b = (t & 15) * 4;

        float4 m = make_float4(0.f, 0.f, 0.f, 0.f);
        #pragma unroll
        for (int dd = 0; dd < CHUNK_D; dd++) {
            const float a = sA[dd * R_RANK + r1];
            const float4 bv = *reinterpret_cast<const float4*>(sB + dd * R_RANK + r2b);
            m.x += a * bv.x; m.y += a * bv.y;
            m.z += a * bv.z; m.w += a * bv.w;
        }
        *reinterpret_cast<float4*>(g_part + (size_t)c * 4096 + r1 * R_RANK + r2b) = m;
        __threadfence();
        __syncthreads();
        if (t == 0)
            atomicAdd(&g_parts, 1u);
        return;
    }

    // ======================= combine + quadform blocks =====================
    {
        const int cb = b - B_COMBINE;        // 0..63, 16 k's each
        float* Msh = pool;                   // 16 KB
        float* fsh = pool + R_RANK * R_RANK; // 4 KB

        // stage F BEFORE waiting (independent of producers; L2-hot)
        reinterpret_cast<float4*>(fsh)[t] =
            reinterpret_cast<const float4*>(F)[(size_t)cb * 256 + t];

        spin_until(&g_parts, NB_PARTIAL);    // all 128 partials visible

        const float4* __restrict__ p4 = reinterpret_cast<const float4*>(g_part);
        float4 acc[4];
        #pragma unroll
        for (int i = 0; i < 4; i++) acc[i] = make_float4(0.f, 0.f, 0.f, 0.f);
        #pragma unroll
        for (int p = 0; p < NCHUNK; p++) {
            #pragma unroll
            for (int i = 0; i < 4; i++) {
                const float4 v = p4[(size_t)p * 1024 + i * 256 + t];
                acc[i].x += v.x; acc[i].y += v.y;
                acc[i].z += v.z; acc[i].w += v.w;
            }
        }
        #pragma unroll
        for (int i = 0; i < 4; i++)
            reinterpret_cast<float4*>(Msh)[i * 256 + t] = acc[i];
        __syncthreads();

        const int w    = t >> 5;
        const int lane = t & 31;
        const float2* __restrict__ M2 = reinterpret_cast<const float2*>(Msh);

        #pragma unroll
        for (int pass = 0; pass < 2; pass++) {
            const int kl = w + pass * 8;
            const float* __restrict__ fk = fsh + kl * R_RANK;

            float2 a2 = make_float2(0.f, 0.f);
            #pragma unroll
            for (int r1 = 0; r1 < R_RANK; r1++) {
                const float fv = fk[r1];
                const float2 mv = M2[r1 * 32 + lane];
                a2.x += fv * mv.x;
                a2.y += fv * mv.y;
            }
            float val = a2.x * fk[2 * lane] + a2.y * fk[2 * lane + 1];

            #pragma unroll
            for (int off = 16; off > 0; off >>= 1)
                val += __shfl_xor_sync(0xffffffffu, val, off);

            if (lane == 0)
                out[cb * 16 + kl] = val * (1.0f / (float)D_DIRS);
        }

        // ---- last combine block resets all counters for the next replay ----
        __syncthreads();
        if (t == 0) {
            __threadfence();
            unsigned old = atomicAdd(&g_done, 1u);
            if (old == (unsigned)(NB_COMBINE - 1)) {
                #pragma unroll
                for (int i = 0; i < NCHUNK; i++) g_ready[i] = 0u;
                g_parts = 0u;
                g_done  = 0u;
                __threadfence();
            }
        }
    }
}

extern "C" void kernel_launch(void* const* d_in, const int* in_sizes, int n_in,
                              void* d_out, int out_size)
{
    const float* atten = (const float*)d_in[0];   // [D,P,R] fp32
    const float* rad   = (const float*)d_in[1];   // [D,P,R] fp32
    const float* F     = (const float*)d_in[2];   // [K,R]   fp32
    float* out = (float*)d_out;                   // [K]     fp32

    (void)in_sizes; (void)n_in; (void)out_size;

    lowrank_kernel<<<NB_TOTAL, 256>>>(atten, rad, F, out);
}

// round 11
// speedup vs baseline: 1.0780x; 1.0780x over previous
#include <cuda_runtime.h>

// Problem shape (fixed by dataset): D=1024, P=256, R=64, K=1024
#define D_DIRS 1024
#define P_PTS  256
#define R_RANK 64
#define K_SUB  1024

#define PREFETCH_BLOCKS 16     // extra blocks in kernel 1 (F warm + g_M zero)

// Scratch (allocation-free rule: __device__ globals)
__device__ float g_asum[D_DIRS * R_RANK];   // sum over p of attenuation
__device__ float g_bsum[D_DIRS * R_RANK];   // sum over p of radiation
__device__ float g_M[R_RANK * R_RANK];      // M accumulator; zeroed by reduce_p
__device__ float g_sink[PREFETCH_BLOCKS];   // keeps F-prefetch alive

// ---------------------------------------------------------------------------
// Kernel 1: reduce over P. One block per (tensor, d) — 2048 short-lived,
// barrier-light blocks (proven ~24-25us @ ~70% DRAM, the practical ceiling).
// 16 extra blocks prefetch F (256 KB) into L2; prefetch block 0 also zeroes
// g_M for this replay's tailA atomics (ordered by the PDL grid dependency;
// the previous replay's tailB finished with g_M before this replay started).
// ---------------------------------------------------------------------------
__global__ __launch_bounds__(256) void reduce_p_kernel(
    const float* __restrict__ atten, const float* __restrict__ rad,
    const float* __restrict__ F)
{
    const int b = blockIdx.x;
    const int t = threadIdx.x;

    if (b >= 2 * D_DIRS) {
        const int pb = b - 2 * D_DIRS;
        if (pb == 0) {
            // zero g_M: 4096 floats = 1024 float4, 4 per thread
            #pragma unroll
            for (int i = 0; i < 4; i++)
                reinterpret_cast<float4*>(g_M)[i * 256 + t] =
                    make_float4(0.f, 0.f, 0.f, 0.f);
        }
        const float4* __restrict__ f4 =
            reinterpret_cast<const float4*>(F) + (size_t)pb * 1024;
        float4 acc = make_float4(0.f, 0.f, 0.f, 0.f);
        #pragma unroll
        for (int i = 0; i < 4; i++) {
            float4 v = f4[i * 256 + t];   // default caching -> lands in L2
            acc.x += v.x; acc.y += v.y; acc.z += v.z; acc.w += v.w;
        }
        if (t == 0) g_sink[pb] = acc.x + acc.y + acc.z + acc.w;
        cudaTriggerProgrammaticLaunchCompletion();
        return;
    }

    const bool is_b = (b >= D_DIRS);
    const int d = b & (D_DIRS - 1);
    const float* __restrict__ src = is_b ? rad : atten;
    float* __restrict__ dst = is_b ? g_bsum : g_asum;

    const float4* __restrict__ in =
        reinterpret_cast<const float4*>(src) + (size_t)d * (P_PTS * R_RANK / 4);

    float4 acc = make_float4(0.f, 0.f, 0.f, 0.f);
    #pragma unroll
    for (int i = 0; i < 16; i++) {
        float4 v = __ldcs(&in[i * 256 + t]);
        acc.x += v.x; acc.y += v.y; acc.z += v.z; acc.w += v.w;
    }

    __shared__ float4 s[256];
    s[t] = acc;
    __syncthreads();

    if (t < 16) {
        float4 sum = s[t];
        #pragma unroll
        for (int j = 1; j < 16; j++) {
            float4 v = s[j * 16 + t];
            sum.x += v.x; sum.y += v.y; sum.z += v.z; sum.w += v.w;
        }
        reinterpret_cast<float4*>(dst + d * R_RANK)[t] = sum;
    }
    cudaTriggerProgrammaticLaunchCompletion();
}

// ---------------------------------------------------------------------------
// Kernel 2 (tailA): partial M over 16 d's per block, atomicAdd into g_M.
// 64 blocks x 256 threads. Stage both 4 KB slices (2 coalesced float4 loads
// per thread per tensor), 256 FMA/thread, then 16 atomics/thread at
// contention depth 64 per address (~0.9us pipelined tail).
// ---------------------------------------------------------------------------
__global__ __launch_bounds__(256) void partial_m_kernel()
{
    __shared__ __align__(16) float sA[16 * R_RANK];   // 4 KB
    __shared__ __align__(16) float sB[16 * R_RANK];   // 4 KB

    const int t = threadIdx.x;
    const int b = blockIdx.x;

    cudaGridDependencySynchronize();   // reduce_p complete (incl. g_M zeroing)

    const float4* __restrict__ a4 =
        reinterpret_cast<const float4*>(g_asum) + (size_t)b * 256;
    const float4* __restrict__ b4 =
        reinterpret_cast<const float4*>(g_bsum) + (size_t)b * 256;
    reinterpret_cast<float4*>(sA)[t] = a4[t];
    reinterpret_cast<float4*>(sB)[t] = b4[t];
    if (t < 0) { }  // (single load per thread covers 256 float4 = 16 rows)
    __syncthreads();

    const int r1  = t >> 2;
    const int r2b = (t & 3) * 16;

    float macc[16];
    #pragma unroll
    for (int j = 0; j < 16; j++) macc[j] = 0.f;

    #pragma unroll
    for (int i = 0; i < 16; i++) {
        const float a = sA[i * R_RANK + r1];
        #pragma unroll
        for (int j = 0; j < 16; j++)
            macc[j] += a * sB[i * R_RANK + r2b + j];
    }

    #pragma unroll
    for (int j = 0; j < 16; j++)
        atomicAdd(&g_M[r1 * R_RANK + r2b + j], macc[j]);

    cudaTriggerProgrammaticLaunchCompletion();
}

// ---------------------------------------------------------------------------
// Kernel 3 (tailB): quadform. 128 blocks x 256 threads, 8 k's per block
// (one warp per k). g_M staged with 4 coalesced float4 loads/thread (L2-hot
// atomics output); F rows L2-hot from prefetch. Plain stores, each out[k]
// written exactly once.
// ---------------------------------------------------------------------------
__global__ __launch_bounds__(256) void quadform_kernel(
    const float* __restrict__ F, float* __restrict__ out)
{
    __shared__ __align__(16) float Msh[R_RANK * R_RANK];   // 16 KB
    __shared__ __align__(16) float fsh[8 * R_RANK];        // 2 KB

    const int t = threadIdx.x;
    const int b = blockIdx.x;

    cudaGridDependencySynchronize();   // all partial_m atomics visible

    #pragma unroll
    for (int i = 0; i < 4; i++)
        reinterpret_cast<float4*>(Msh)[i * 256 + t] =
            reinterpret_cast<const float4*>(g_M)[i * 256 + t];

    if (t < 128)
        reinterpret_cast<float4*>(fsh)[t] =
            reinterpret_cast<const float4*>(F)[(size_t)b * 128 + t];
    __syncthreads();

    const int w    = t >> 5;
    const int lane = t & 31;
    const float* __restrict__ fk = fsh + w * R_RANK;
    const float2* __restrict__ M2 = reinterpret_cast<const float2*>(Msh);

    float2 a2 = make_float2(0.f, 0.f);
    #pragma unroll
    for (int r1 = 0; r1 < R_RANK; r1++) {
        const float fv = fk[r1];               // warp-uniform broadcast
        const float2 mv = M2[r1 * 32 + lane];
        a2.x += fv * mv.x;
        a2.y += fv * mv.y;
    }
    float val = a2.x * fk[2 * lane] + a2.y * fk[2 * lane + 1];

    #pragma unroll
    for (int off = 16; off > 0; off >>= 1)
        val += __shfl_xor_sync(0xffffffffu, val, off);

    if (lane == 0)
        out[b * 8 + w] = val * (1.0f / (float)D_DIRS);
}

extern "C" void kernel_launch(void* const* d_in, const int* in_sizes, int n_in,
                              void* d_out, int out_size)
{
    const float* atten = (const float*)d_in[0];   // [D,P,R] fp32
    const float* rad   = (const float*)d_in[1];   // [D,P,R] fp32
    const float* F     = (const float*)d_in[2];   // [K,R]   fp32
    float* out = (float*)d_out;                   // [K]     fp32

    (void)in_sizes; (void)n_in; (void)out_size;

    reduce_p_kernel<<<2 * D_DIRS + PREFETCH_BLOCKS, 256>>>(atten, rad, F);

    // PDL: dependent kernels dispatched early, wait at
    // cudaGridDependencySynchronize, hiding the per-launch constant.
    cudaLaunchAttribute attr[1];
    attr[0].id = cudaLaunchAttributeProgrammaticStreamSerialization;
    attr[0].val.programmaticStreamSerializationAllowed = 1;

    cudaLaunchConfig_t cfg = {};
    cfg.blockDim = dim3(256, 1, 1);
    cfg.attrs = attr;
    cfg.numAttrs = 1;
    cfg.stream = 0;

    cfg.gridDim = dim3(64, 1, 1);
    cudaLaunchKernelEx(&cfg, partial_m_kernel);

    cfg.gridDim = dim3(128, 1, 1);
    cudaLaunchKernelEx(&cfg, quadform_kernel, F, out);
}

// round 12
// speedup vs baseline: 1.3066x; 1.2120x over previous
#include <cuda_runtime.h>
#include <cstdint>

// Problem shape (fixed by dataset): D=1024, P=256, R=64, K=1024
#define D_DIRS 1024
#define P_PTS  256
#define R_RANK 64
#define K_SUB  1024

#define PREFETCH_BLOCKS 16     // extra blocks in kernel 1 that warm L2 with F
#define NCHUNK 16              // d-chunks for partial M
#define CHUNK_D (D_DIRS / NCHUNK)   // 64 directions per chunk

#define TMA_CHUNK_BYTES 16384  // 16 KB per bulk copy; 4 chunks per 64 KB slab

// Scratch (allocation-free rule: __device__ globals; fully rewritten each
// replay — no zeroing, no atomics anywhere)
__device__ float g_asum[D_DIRS * R_RANK];
__device__ float g_bsum[D_DIRS * R_RANK];
__device__ float g_part[NCHUNK * R_RANK * R_RANK];   // 256 KB
__device__ float g_sink[PREFETCH_BLOCKS];

// ---------------- mbarrier / bulk-copy helpers ----------------
__device__ __forceinline__ uint32_t smem_u32(const void* p)
{
    uint32_t a;
    asm("{ .reg .u64 tmp; cvta.to.shared.u64 tmp, %1; cvt.u32.u64 %0, tmp; }"
        : "=r"(a) : "l"(p));
    return a;
}
__device__ __forceinline__ void mbar_init(uint32_t mbar, uint32_t count)
{
    asm volatile("mbarrier.init.shared.b64 [%0], %1;" :: "r"(mbar), "r"(count) : "memory");
}
__device__ __forceinline__ void mbar_expect_tx(uint32_t mbar, uint32_t bytes)
{
    asm volatile("mbarrier.arrive.expect_tx.shared.b64 _, [%0], %1;"
                 :: "r"(mbar), "r"(bytes) : "memory");
}
__device__ __forceinline__ void bulk_g2s(uint32_t dst_smem, const void* src_gmem,
                                         uint32_t bytes, uint32_t mbar)
{
    asm volatile(
        "cp.async.bulk.shared::cluster.global.mbarrier::complete_tx::bytes "
        "[%0], [%1], %2, [%3];"
        :: "r"(dst_smem), "l"(src_gmem), "r"(bytes), "r"(mbar) : "memory");
}
__device__ __forceinline__ void mbar_wait(uint32_t mbar, uint32_t phase)
{
    asm volatile(
        "{\n\t.reg .pred P;\n\t"
        "WAIT_%=:\n\t"
        "mbarrier.try_wait.parity.shared::cta.b64 P, [%0], %1;\n\t"
        "@!P bra WAIT_%=;\n\t"
        "}"
        :: "r"(mbar), "r"(phase) : "memory");
}

// ---------------------------------------------------------------------------
// Kernel 1: reduce over P via TMA bulk-copy pipeline.
// One block per (tensor, d); each block streams its 64 KB slab as 4 x 16 KB
// cp.async.bulk bursts (double-buffered, mbarrier-signaled). Long contiguous
// DRAM bursts -> better HBM row locality than per-warp 512B LDG requests.
// Accumulation mapping identical to the proven LDG version (index q*256+t).
// 16 extra blocks prefetch F (256 KB) into L2 for the tail.
// ---------------------------------------------------------------------------
__global__ __launch_bounds__(256) void reduce_p_kernel(
    const float* __restrict__ atten, const float* __restrict__ rad,
    const float* __restrict__ F)
{
    __shared__ __align__(1024) float4 buf[2][1024];   // 2 x 16 KB
    __shared__ uint64_t mb[2];

    const int b = blockIdx.x;
    const int t = threadIdx.x;

    if (b >= 2 * D_DIRS) {
        // ---- F prefetch: 16 blocks x 16 KB = 256 KB into L2 ----
        const int pb = b - 2 * D_DIRS;
        const float4* __restrict__ f4 =
            reinterpret_cast<const float4*>(F) + (size_t)pb * 1024;
        float4 acc = make_float4(0.f, 0.f, 0.f, 0.f);
        #pragma unroll
        for (int i = 0; i < 4; i++) {
            float4 v = f4[i * 256 + t];
            acc.x += v.x; acc.y += v.y; acc.z += v.z; acc.w += v.w;
        }
        if (t == 0) g_sink[pb] = acc.x + acc.y + acc.z + acc.w;
        cudaTriggerProgrammaticLaunchCompletion();
        return;
    }

    const bool is_b = (b >= D_DIRS);
    const int d = b & (D_DIRS - 1);
    const float* __restrict__ src = is_b ? rad : atten;
    float* __restrict__ dst = is_b ? g_bsum : g_asum;
    const char* slab = reinterpret_cast<const char*>(src)
                       + (size_t)d * (P_PTS * R_RANK * sizeof(float));

    const uint32_t mb0  = smem_u32(&mb[0]);
    const uint32_t mb1  = smem_u32(&mb[1]);
    const uint32_t buf0 = smem_u32(&buf[0][0]);
    const uint32_t buf1 = smem_u32(&buf[1][0]);

    if (t == 0) {
        mbar_init(mb0, 1);
        mbar_init(mb1, 1);
    }
    __syncthreads();

    if (t == 0) {
        mbar_expect_tx(mb0, TMA_CHUNK_BYTES);
        bulk_g2s(buf0, slab + 0 * TMA_CHUNK_BYTES, TMA_CHUNK_BYTES, mb0);
        mbar_expect_tx(mb1, TMA_CHUNK_BYTES);
        bulk_g2s(buf1, slab + 1 * TMA_CHUNK_BYTES, TMA_CHUNK_BYTES, mb1);
    }

    float4 acc = make_float4(0.f, 0.f, 0.f, 0.f);

    // ---- chunk 0 (buf0, phase 0) ----
    mbar_wait(mb0, 0);
    #pragma unroll
    for (int q = 0; q < 4; q++) {
        float4 v = buf[0][q * 256 + t];
        acc.x += v.x; acc.y += v.y; acc.z += v.z; acc.w += v.w;
    }
    __syncthreads();
    if (t == 0) {
        mbar_expect_tx(mb0, TMA_CHUNK_BYTES);
        bulk_g2s(buf0, slab + 2 * TMA_CHUNK_BYTES, TMA_CHUNK_BYTES, mb0);
    }

    // ---- chunk 1 (buf1, phase 0) ----
    mbar_wait(mb1, 0);
    #pragma unroll
    for (int q = 0; q < 4; q++) {
        float4 v = buf[1][q * 256 + t];
        acc.x += v.x; acc.y += v.y; acc.z += v.z; acc.w += v.w;
    }
    __syncthreads();
    if (t == 0) {
        mbar_expect_tx(mb1, TMA_CHUNK_BYTES);
        bulk_g2s(buf1, slab + 3 * TMA_CHUNK_BYTES, TMA_CHUNK_BYTES, mb1);
    }

    // ---- chunk 2 (buf0, phase 1) ----
    mbar_wait(mb0, 1);
    #pragma unroll
    for (int q = 0; q < 4; q++) {
        float4 v = buf[0][q * 256 + t];
        acc.x += v.x; acc.y += v.y; acc.z += v.z; acc.w += v.w;
    }

    // ---- chunk 3 (buf1, phase 1) ----
    mbar_wait(mb1, 1);
    #pragma unroll
    for (int q = 0; q < 4; q++) {
        float4 v = buf[1][q * 256 + t];
        acc.x += v.x; acc.y += v.y; acc.z += v.z; acc.w += v.w;
    }

    // ---- tree reduce (same mapping as proven LDG kernel) ----
    // reuse buf[0] (chunk 2 fully consumed by all readers of each slot:
    // thread t writes only slot t, which only thread t reads)
    float4* s = &buf[0][0];
    s[t] = acc;
    __syncthreads();

    if (t < 16) {
        float4 sum = s[t];
        #pragma unroll
        for (int j = 1; j < 16; j++) {
            float4 v = s[j * 16 + t];
            sum.x += v.x; sum.y += v.y; sum.z += v.z; sum.w += v.w;
        }
        reinterpret_cast<float4*>(dst + d * R_RANK)[t] = sum;
    }
    cudaTriggerProgrammaticLaunchCompletion();
}

// ---------------------------------------------------------------------------
// Kernel 2 (PDL): partial M. 64 blocks = (chunk c = b>>2 of 64 d's,
// r1-quarter q = b&3). Stage both 16 KB chunk slices in smem, 256 FMA/thread,
// plain float4 stores to g_part. No atomics.
// ---------------------------------------------------------------------------
__global__ __launch_bounds__(256) void partial_m_kernel()
{
    __shared__ __align__(16) float sA[CHUNK_D * R_RANK];   // 16 KB
    __shared__ __align__(16) float sB[CHUNK_D * R_RANK];   // 16 KB

    const int t = threadIdx.x;
    const int c = blockIdx.x >> 2;
    const int q = blockIdx.x & 3;

    cudaGridDependencySynchronize();   // reduce_p's writes visible

    const float4* __restrict__ a4 =
        reinterpret_cast<const float4*>(g_asum) + (size_t)c * 1024;
    const float4* __restrict__ b4 =
        reinterpret_cast<const float4*>(g_bsum) + (size_t)c * 1024;
    #pragma unroll
    for (int i = 0; i < 4; i++) {
        reinterpret_cast<float4*>(sA)[i * 256 + t] = a4[i * 256 + t];
        reinterpret_cast<float4*>(sB)[i * 256 + t] = b4[i * 256 + t];
    }
    __syncthreads();

    const int r1  = q * 16 + (t >> 4);
    const int r2b = (t & 15) * 4;

    float4 m = make_float4(0.f, 0.f, 0.f, 0.f);
    #pragma unroll
    for (int dd = 0; dd < CHUNK_D; dd++) {
        const float a = sA[dd * R_RANK + r1];
        const float4 bv = *reinterpret_cast<const float4*>(sB + dd * R_RANK + r2b);
        m.x += a * bv.x; m.y += a * bv.y;
        m.z += a * bv.z; m.w += a * bv.w;
    }

    *reinterpret_cast<float4*>(g_part + (size_t)c * 4096 + r1 * R_RANK + r2b) = m;
    cudaTriggerProgrammaticLaunchCompletion();
}

// ---------------------------------------------------------------------------
// Kernel 3 (PDL): combine + quadform. 64 blocks x 256 threads, 16 k's each.
// F staged BEFORE the grid dependency (input tensor, independent of
// producers) to overlap its latency with the stream. Then combine M from the
// 16 L2-hot partials and run the quadform. Plain stores to out.
// ---------------------------------------------------------------------------
__global__ __launch_bounds__(256) void combine_quad_kernel(
    const float* __restrict__ F, float* __restrict__ out)
{
    __shared__ __align__(16) float Msh[R_RANK * R_RANK];   // 16 KB
    __shared__ __align__(16) float fsh[16 * R_RANK];       // 4 KB

    const int t = threadIdx.x;
    const int b = blockIdx.x;

    // prestage F (independent of predecessor kernels)
    reinterpret_cast<float4*>(fsh)[t] =
        reinterpret_cast<const float4*>(F)[(size_t)b * 256 + t];

    cudaGridDependencySynchronize();   // partial_m's writes visible

    const float4* __restrict__ p4 = reinterpret_cast<const float4*>(g_part);
    float4 acc[4];
    #pragma unroll
    for (int i = 0; i < 4; i++) acc[i] = make_float4(0.f, 0.f, 0.f, 0.f);

    #pragma unroll
    for (int p = 0; p < NCHUNK; p++) {
        #pragma unroll
        for (int i = 0; i < 4; i++) {
            const float4 v = p4[(size_t)p * 1024 + i * 256 + t];
            acc[i].x += v.x; acc[i].y += v.y;
            acc[i].z += v.z; acc[i].w += v.w;
        }
    }
    #pragma unroll
    for (int i = 0; i < 4; i++)
        reinterpret_cast<float4*>(Msh)[i * 256 + t] = acc[i];
    __syncthreads();

    const int w    = t >> 5;
    const int lane = t & 31;
    const float2* __restrict__ M2 = reinterpret_cast<const float2*>(Msh);

    #pragma unroll
    for (int pass = 0; pass < 2; pass++) {
        const int kl = w + pass * 8;
        const float* __restrict__ fk = fsh + kl * R_RANK;

        float2 a2 = make_float2(0.f, 0.f);
        #pragma unroll
        for (int r1 = 0; r1 < R_RANK; r1++) {
            const float fv = fk[r1];
            const float2 mv = M2[r1 * 32 + lane];
            a2.x += fv * mv.x;
            a2.y += fv * mv.y;
        }
        float val = a2.x * fk[2 * lane] + a2.y * fk[2 * lane + 1];

        #pragma unroll
        for (int off = 16; off > 0; off >>= 1)
            val += __shfl_xor_sync(0xffffffffu, val, off);

        if (lane == 0)
            out[b * 16 + kl] = val * (1.0f / (float)D_DIRS);
    }
}

extern "C" void kernel_launch(void* const* d_in, const int* in_sizes, int n_in,
                              void* d_out, int out_size)
{
    const float* atten = (const float*)d_in[0];   // [D,P,R] fp32
    const float* rad   = (const float*)d_in[1];   // [D,P,R] fp32
    const float* F     = (const float*)d_in[2];   // [K,R]   fp32
    float* out = (float*)d_out;                   // [K]     fp32

    (void)in_sizes; (void)n_in; (void)out_size;

    reduce_p_kernel<<<2 * D_DIRS + PREFETCH_BLOCKS, 256>>>(atten, rad, F);

    cudaLaunchAttribute attr[1];
    attr[0].id = cudaLaunchAttributeProgrammaticStreamSerialization;
    attr[0].val.programmaticStreamSerializationAllowed = 1;

    cudaLaunchConfig_t cfg = {};
    cfg.blockDim = dim3(256, 1, 1);
    cfg.attrs = attr;
    cfg.numAttrs = 1;
    cfg.stream = 0;

    cfg.gridDim = dim3(64, 1, 1);
    cudaLaunchKernelEx(&cfg, partial_m_kernel);

    cfg.gridDim = dim3(64, 1, 1);
    cudaLaunchKernelEx(&cfg, combine_quad_kernel, F, out);
}